// round 17
// baseline (speedup 1.0000x reference)
#include <cuda_runtime.h>
#include <cuda_fp16.h>
#include <cstdint>

// ============================================================
// out = diag(1/(rowsum(adj)+beta)) @ (adj + diag(beta)) @ x @ W + bias
// R16 regressed (split-K x4 + fused combine, -17us on B+combine) -> revert
// to R15 structure. R17 increments:
//  * kernel B: 4 -> 5-stage B ring (wait_group 3), smem 94.7KB x2/SM.
//  * kernel A converts x fp32->fp16 inline (convert kernel now W-only).
// ============================================================

#define NN 8192
#define FF 256
#define MT 64             // CTA M tile (kernel B)
#define KS 32             // K per stage (kernel B)
#define KSPLIT 4096       // K per CTA (split-K x2)
#define NITER (KSPLIT / KS)  // 128
#define KSPA 40           // A row stride in halves (80B)
#define KSPB 264          // B row stride in halves (528B, trans-ldm conflict-free)
#define AS_STAGE (MT * KSPA)        // 2560 halves
#define AS_STAGE_B (AS_STAGE * 2)   // 5120 B
#define BS_STAGE (KS * KSPB)        // 8448 halves
#define BS_STAGE_B (BS_STAGE * 2)   // 16896 B
#define NSTAGEB 5

#define OFF_AS    0                                 // 2 stages * 5120
#define OFF_BS    (2 * AS_STAGE_B)                  // 10240
#define SMEM_TOTAL (OFF_BS + NSTAGEB * BS_STAGE_B)  // 94720 (x2 CTAs = 189440/SM)

// kernel A (single-load) layout
#define KSPX 264          // x row stride in halves (528B)
#define KSPW 72           // W row stride in halves (144B)
#define OFF_WS (64 * KSPX * 2)                       // 33792
#define SMEM_A_TOTAL (OFF_WS + 256 * KSPW * 2)       // 70656 (x2 = 141312/SM)

__device__ __align__(256) __half g_wh[FF * FF];       // W fp16
__device__ __align__(256) __half g_yh[NN * FF];       // y fp16 (row-major)
__device__ __align__(256) float  g_part[2 * NN * FF]; // split-K partial C
__device__ __align__(256) float  g_rs[2 * NN];        // split-K partial rowsum

// ---------------- helpers ----------------
__device__ __forceinline__ uint32_t smem_u32(const void* p) {
    uint32_t a;
    asm("{ .reg .u64 t; cvta.to.shared.u64 t, %1; cvt.u32.u64 %0, t; }" : "=r"(a) : "l"(p));
    return a;
}
__device__ __forceinline__ void cp16(uint32_t dst, const void* src) {
    asm volatile("cp.async.cg.shared.global [%0], [%1], 16;" :: "r"(dst), "l"(src));
}
__device__ __forceinline__ void cp_commit() {
    asm volatile("cp.async.commit_group;" ::: "memory");
}
__device__ __forceinline__ void ldm_x4(uint32_t* r, uint32_t addr) {
    asm volatile("ldmatrix.sync.aligned.m8n8.x4.shared.b16 {%0,%1,%2,%3}, [%4];"
        : "=r"(r[0]), "=r"(r[1]), "=r"(r[2]), "=r"(r[3]) : "r"(addr));
}
__device__ __forceinline__ void ldm_x4_t(uint32_t* r, uint32_t addr) {
    asm volatile("ldmatrix.sync.aligned.m8n8.x4.trans.shared.b16 {%0,%1,%2,%3}, [%4];"
        : "=r"(r[0]), "=r"(r[1]), "=r"(r[2]), "=r"(r[3]) : "r"(addr));
}
__device__ __forceinline__ void mma_f16(float* c, const uint32_t* a, uint32_t b0, uint32_t b1) {
    asm volatile(
        "mma.sync.aligned.m16n8k16.row.col.f32.f16.f16.f32 "
        "{%0,%1,%2,%3}, {%4,%5,%6,%7}, {%8,%9}, {%0,%1,%2,%3};"
        : "+f"(c[0]), "+f"(c[1]), "+f"(c[2]), "+f"(c[3])
        : "r"(a[0]), "r"(a[1]), "r"(a[2]), "r"(a[3]), "r"(b0), "r"(b1));
}

// ---------------- pre-pass: fp32 -> fp16 for W only ----------------
__global__ void __launch_bounds__(256) convert_kernel(const float* __restrict__ w)
{
    const int j = blockIdx.x * 256 + threadIdx.x;     // 1 thread = 8 floats
    const float4 v0 = *(const float4*)&w[(size_t)j * 8];
    const float4 v1 = *(const float4*)&w[(size_t)j * 8 + 4];
    __half2 h[4];
    h[0] = __floats2half2_rn(v0.x, v0.y); h[1] = __floats2half2_rn(v0.z, v0.w);
    h[2] = __floats2half2_rn(v1.x, v1.y); h[3] = __floats2half2_rn(v1.z, v1.w);
    *(uint4*)&g_wh[(size_t)j * 8] = make_uint4(
        *(uint32_t*)&h[0], *(uint32_t*)&h[1], *(uint32_t*)&h[2], *(uint32_t*)&h[3]);
}

// ---------------- kernel A: y = x @ W (fp16 HMMA), single-barrier ----------------
// CTA 64m x 64n, grid (128, 4) = 512 CTAs, 256 thr, 8 warps (2m x 4n), warp 32x16.
// x is read fp32 and converted inline during staging.
__global__ void __launch_bounds__(256, 2) gemm_y_kernel(const float* __restrict__ x)
{
    extern __shared__ char smem[];
    __half* xs = (__half*)smem;
    const uint32_t sb = smem_u32(smem);
    const int tid = threadIdx.x;
    const int wid = tid >> 5, lane = tid & 31;
    const int g = lane >> 2, t = lane & 3;
    const int wm = wid & 1, wn = wid >> 1;
    const int m0 = blockIdx.x * 64;
    const int n0 = blockIdx.y * 64;
    const int mt8 = lane >> 3, r8 = lane & 7;

    // ---- W slice [256k][64n] via cp.async (fp16 source) ----
    {
        const int wr = tid >> 3, wc = tid & 7;
        #pragma unroll
        for (int p = 0; p < 8; p++) {
            const int row = p * 32 + wr;
            cp16(sb + OFF_WS + (uint32_t)(row * KSPW + wc * 8) * 2,
                 (const void*)(g_wh + (size_t)row * FF + n0 + wc * 8));
        }
    }
    cp_commit();

    // ---- x tile [64m][256k]: fp32 LDG -> cvt -> STS (one shot) ----
    {
        const int xr = tid >> 2;             // 64 rows, 4 thr/row
        const int xc = (tid & 3) * 64;       // 64 floats each
        const float* xp = x + (size_t)(m0 + xr) * FF + xc;
        #pragma unroll
        for (int j = 0; j < 8; j++) {
            const float4 v0 = *(const float4*)(xp + j * 8);
            const float4 v1 = *(const float4*)(xp + j * 8 + 4);
            __half2 h[4];
            h[0] = __floats2half2_rn(v0.x, v0.y); h[1] = __floats2half2_rn(v0.z, v0.w);
            h[2] = __floats2half2_rn(v1.x, v1.y); h[3] = __floats2half2_rn(v1.z, v1.w);
            *(uint4*)&xs[xr * KSPX + xc + j * 8] = make_uint4(
                *(uint32_t*)&h[0], *(uint32_t*)&h[1], *(uint32_t*)&h[2], *(uint32_t*)&h[3]);
        }
    }
    asm volatile("cp.async.wait_group 0;" ::: "memory");
    __syncthreads();

    const uint32_t a_lm = sb +
        (uint32_t)(((wm * 32 + (mt8 & 1) * 8 + r8) * KSPX + (mt8 >> 1) * 8) * 2);
    const uint32_t b_lm = sb + OFF_WS +
        (uint32_t)(((r8 + (mt8 & 1) * 8) * KSPW + wn * 16 + (mt8 >> 1) * 8) * 2);

    float acc[2][2][4];
    #pragma unroll
    for (int i = 0; i < 2; i++)
        #pragma unroll
        for (int j = 0; j < 2; j++)
            #pragma unroll
            for (int q = 0; q < 4; q++) acc[i][j][q] = 0.f;

    #pragma unroll
    for (int kk = 0; kk < 16; kk++) {
        uint32_t a0[4], a1[4], bf[4];
        ldm_x4(a0, a_lm + kk * 32);
        ldm_x4(a1, a_lm + kk * 32 + 16 * KSPX * 2);
        ldm_x4_t(bf, b_lm + (uint32_t)(kk * 16 * KSPW) * 2);
        mma_f16(acc[0][0], a0, bf[0], bf[1]);
        mma_f16(acc[0][1], a0, bf[2], bf[3]);
        mma_f16(acc[1][0], a1, bf[0], bf[1]);
        mma_f16(acc[1][1], a1, bf[2], bf[3]);
    }

    // epilogue: write fp16 y only
    #pragma unroll
    for (int mi = 0; mi < 2; mi++) {
        const int lm = wm * 32 + mi * 16 + g;
        #pragma unroll
        for (int nj = 0; nj < 2; nj++) {
            const int n = n0 + wn * 16 + nj * 8 + 2 * t;
            const float* cc = acc[mi][nj];
            *(__half2*)&g_yh[(size_t)(m0 + lm) * FF + n]     = __floats2half2_rn(cc[0], cc[1]);
            *(__half2*)&g_yh[(size_t)(m0 + lm + 8) * FF + n] = __floats2half2_rn(cc[2], cc[3]);
        }
    }
}

// ---------------- kernel B: partial C = adj[:, kslice] @ y[kslice] ----------------
// 256 thr, 8 warps (2m x 4n), warp tile 32x64, CTA 64x256, split-K x2, 5-stage ring.
__global__ void __launch_bounds__(256, 2) gcn_mma_kernel(
    const float* __restrict__ adj)
{
    extern __shared__ char smem[];
    __half* As = (__half*)(smem + OFF_AS);
    const uint32_t sb = smem_u32(smem);

    const int tid = threadIdx.x;
    const int wid = tid >> 5, lane = tid & 31;
    const int g = lane >> 2, t = lane & 3;
    const int wm = wid & 1, wn = wid >> 1;      // 2 m-warps x 4 n-warps
    const int m0 = blockIdx.x * MT;
    const int ksl = blockIdx.y;                 // 0 or 1
    const int k0 = ksl * KSPLIT;

    // A: 4 threads per row, 8 floats each (KS=32)
    const int ar = tid >> 2, acq = tid & 3;
    const float* aptr = adj + (size_t)(m0 + ar) * NN + k0 + acq * 8;
    __half* const a_st = As + ar * KSPA + acq * 8;
    // B: 32 threads per k-row, contiguous 16B; 8 rows/pass, 4 passes/stage
    const int br = tid >> 5, bq = tid & 31;
    const __half* bptr = g_yh + (size_t)(k0 + br) * FF + bq * 8;
    const uint32_t b_dst = sb + OFF_BS + (br * KSPB) * 2 + bq * 16;

    const int mt8 = lane >> 3, r8 = lane & 7;
    const uint32_t a_lm = sb + OFF_AS +
        (((wm * 32 + (mt8 & 1) * 8 + r8) * KSPA + (mt8 >> 1) * 8) * 2);
    const uint32_t b_lm = sb + OFF_BS +
        (((r8 + (mt8 & 1) * 8) * KSPB + wn * 64 + (mt8 >> 1) * 8) * 2);

    float rs_local = 0.f;
    float acc[2][8][4];
    #pragma unroll
    for (int i = 0; i < 2; i++)
        #pragma unroll
        for (int j = 0; j < 8; j++)
            #pragma unroll
            for (int q = 0; q < 4; q++) acc[i][j][q] = 0.f;

    float4 ra[2][2];

    // ---- prologue: B stages 0..3 via cp.async; A stages 0,1 via LDG ----
    #pragma unroll
    for (int s = 0; s < 4; s++) {
        #pragma unroll
        for (int c = 0; c < 4; c++)
            cp16(b_dst + s * BS_STAGE_B + c * (8 * KSPB * 2),
                 (const void*)(bptr + ((size_t)s * KS + c * 8) * FF));
        cp_commit();
    }
    #pragma unroll
    for (int s = 0; s < 2; s++) {
        ra[s][0] = *(const float4*)(aptr + (size_t)s * KS);
        ra[s][1] = *(const float4*)(aptr + (size_t)s * KS + 4);
    }
    {   // STS A stage 0 + rowsum
        const float4 v0 = ra[0][0], v1 = ra[0][1];
        rs_local += v0.x + v0.y + v0.z + v0.w + v1.x + v1.y + v1.z + v1.w;
        __half2 h[4];
        h[0] = __floats2half2_rn(v0.x, v0.y); h[1] = __floats2half2_rn(v0.z, v0.w);
        h[2] = __floats2half2_rn(v1.x, v1.y); h[3] = __floats2half2_rn(v1.z, v1.w);
        *(uint4*)a_st = make_uint4(*(uint32_t*)&h[0], *(uint32_t*)&h[1],
                                   *(uint32_t*)&h[2], *(uint32_t*)&h[3]);
    }

    // ---- main loop (single barrier, 5-stage B ring, 3 stages in flight) ----
    int bbuf = 0;     // = i % 5
    int pbuf = 4;     // = (i + 4) % 5
    for (int i = 0; i < NITER; i++) {
        if (i + 2 < NITER) {
            const float* ap = aptr + (size_t)(i + 2) * KS;
            ra[i & 1][0] = *(const float4*)(ap);
            ra[i & 1][1] = *(const float4*)(ap + 4);
        }

        if (i < NITER - 3)       { asm volatile("cp.async.wait_group 3;" ::: "memory"); }
        else if (i == NITER - 3) { asm volatile("cp.async.wait_group 2;" ::: "memory"); }
        else if (i == NITER - 2) { asm volatile("cp.async.wait_group 1;" ::: "memory"); }
        else                     { asm volatile("cp.async.wait_group 0;" ::: "memory"); }
        __syncthreads();

        if (i + 1 < NITER) {   // STS A stage i+1 + rowsum
            const float4 v0 = ra[(i + 1) & 1][0], v1 = ra[(i + 1) & 1][1];
            rs_local += v0.x + v0.y + v0.z + v0.w + v1.x + v1.y + v1.z + v1.w;
            __half2 h[4];
            h[0] = __floats2half2_rn(v0.x, v0.y); h[1] = __floats2half2_rn(v0.z, v0.w);
            h[2] = __floats2half2_rn(v1.x, v1.y); h[3] = __floats2half2_rn(v1.z, v1.w);
            *(uint4*)(a_st + ((i + 1) & 1) * AS_STAGE) = make_uint4(
                *(uint32_t*)&h[0], *(uint32_t*)&h[1], *(uint32_t*)&h[2], *(uint32_t*)&h[3]);
        }
        if (i + 4 < NITER) {   // cp.async B stage i+4 into buf (i+4)%5 (== i-1, free)
            const uint32_t bd = b_dst + pbuf * BS_STAGE_B;
            const __half* bp = bptr + (size_t)(i + 4) * KS * FF;
            #pragma unroll
            for (int c = 0; c < 4; c++)
                cp16(bd + c * (8 * KSPB * 2), (const void*)(bp + (size_t)c * 8 * FF));
            cp_commit();
        }

        // ---- compute stage i (warp tile 32x64, 2 kk chunks) ----
        const uint32_t aB = a_lm + (i & 1) * AS_STAGE_B;
        const uint32_t bB = b_lm + bbuf * BS_STAGE_B;
        #pragma unroll
        for (int kk = 0; kk < 2; kk++) {
            uint32_t a0[4], a1[4];
            ldm_x4(a0, aB + kk * 32);
            ldm_x4(a1, aB + kk * 32 + 16 * KSPA * 2);
            uint32_t bf[4][4];
            #pragma unroll
            for (int j = 0; j < 4; j++)
                ldm_x4_t(bf[j], bB + (uint32_t)(kk * 16 * KSPB) * 2 + j * 32);
            #pragma unroll
            for (int j = 0; j < 4; j++) {
                mma_f16(acc[0][2 * j],     a0, bf[j][0], bf[j][1]);
                mma_f16(acc[0][2 * j + 1], a0, bf[j][2], bf[j][3]);
                mma_f16(acc[1][2 * j],     a1, bf[j][0], bf[j][1]);
                mma_f16(acc[1][2 * j + 1], a1, bf[j][2], bf[j][3]);
            }
        }

        bbuf = (bbuf == NSTAGEB - 1) ? 0 : bbuf + 1;
        pbuf = (pbuf == NSTAGEB - 1) ? 0 : pbuf + 1;
    }

    // ---- partial rowsum: 4 consecutive lanes per row ----
    float rs = rs_local;
    rs += __shfl_xor_sync(0xffffffffu, rs, 1);
    rs += __shfl_xor_sync(0xffffffffu, rs, 2);
    if ((tid & 3) == 0) g_rs[(size_t)ksl * NN + m0 + ar] = rs;

    // ---- write partial C ----
    float* pout = g_part + (size_t)ksl * NN * FF;
    #pragma unroll
    for (int mi = 0; mi < 2; mi++) {
        const int lm = wm * 32 + mi * 16 + g;
        #pragma unroll
        for (int nj = 0; nj < 8; nj++) {
            const int n = wn * 64 + nj * 8 + 2 * t;
            const float* cc = acc[mi][nj];
            *(float2*)&pout[(size_t)(m0 + lm) * FF + n]     = make_float2(cc[0], cc[1]);
            *(float2*)&pout[(size_t)(m0 + lm + 8) * FF + n] = make_float2(cc[2], cc[3]);
        }
    }
}

// ---------------- combine: out = scale*(P0+P1+beta*y) + bias ----------------
__global__ void __launch_bounds__(256) combine_kernel(
    const float* __restrict__ beta,
    const float* __restrict__ bias,
    float* __restrict__ out)
{
    const int idx = blockIdx.x * 256 + threadIdx.x;   // 1 thread = 4 floats
    const int m = idx >> 6;
    const int n = (idx & 63) * 4;
    const float be = beta[m];
    const float sc = 1.0f / (g_rs[m] + g_rs[NN + m] + be);
    const size_t off = (size_t)m * FF + n;
    const float4 p0 = *(const float4*)&g_part[off];
    const float4 p1 = *(const float4*)&g_part[(size_t)NN * FF + off];
    const uint2 yraw = *(const uint2*)&g_yh[off];     // 4 halves
    const float2 ya = __half22float2(*(const __half2*)&yraw.x);
    const float2 yb = __half22float2(*(const __half2*)&yraw.y);
    const float4 bv = *(const float4*)&bias[n];
    float4 o;
    o.x = sc * (p0.x + p1.x + be * ya.x) + bv.x;
    o.y = sc * (p0.y + p1.y + be * ya.y) + bv.y;
    o.z = sc * (p0.z + p1.z + be * yb.x) + bv.z;
    o.w = sc * (p0.w + p1.w + be * yb.y) + bv.w;
    *(float4*)&out[off] = o;
}

// ---------------- launch ----------------
extern "C" void kernel_launch(void* const* d_in, const int* in_sizes, int n_in,
                              void* d_out, int out_size)
{
    const float *x = nullptr, *adj = nullptr, *w = nullptr, *bias = nullptr, *beta = nullptr;
    for (int i = 0; i < n_in; i++) {
        switch (in_sizes[i]) {
            case NN * FF:   x    = (const float*)d_in[i]; break;
            case 67108864:  adj  = (const float*)d_in[i]; break;
            case FF * FF:   w    = (const float*)d_in[i]; break;
            case FF:        bias = (const float*)d_in[i]; break;
            case NN:        beta = (const float*)d_in[i]; break;
            default: break;
        }
    }
    float* out = (float*)d_out;

    cudaFuncSetAttribute(gcn_mma_kernel, cudaFuncAttributeMaxDynamicSharedMemorySize, SMEM_TOTAL);
    cudaFuncSetAttribute(gemm_y_kernel, cudaFuncAttributeMaxDynamicSharedMemorySize, SMEM_A_TOTAL);

    convert_kernel<<<(FF * FF / 8) / 256, 256>>>(w);
    gemm_y_kernel<<<dim3(NN / 64, 4), 256, SMEM_A_TOTAL>>>(x);
    gcn_mma_kernel<<<dim3(NN / MT, 2), 256, SMEM_TOTAL>>>(adj);
    combine_kernel<<<(NN * FF) / (256 * 4), 256>>>(beta, bias, out);
}